// round 7
// baseline (speedup 1.0000x reference)
#include <cuda_runtime.h>
#include <math.h>
#include <stdint.h>

#define Bk   128
#define Hk   512
#define Tk   1024
#define INk  8
#define OUTk 2

#define JB    8         // j-slice CTAs per batch-group
#define NPAIR 8         // batch-group pairs
#define NGRP  2         // groups per CTA (interleaved)
#define HJ   64         // H / JB
#define BC   8          // batches per group
#define NCTA 64         // JB * NPAIR
#define NTHR 512        // 16 warps
#define NW   16
#define STEPS (Tk - 1)

typedef unsigned long long ull;

// ---------------- device globals ----------------
// bb = pair*2 + g  (16 batch-groups of 8 batches)
__device__ float g_h[2][16][JB][BC * HJ];     // h ping-pong, sliced
__device__ int   g_flag[16][JB][8];           // latest published step per (bb, jb)
__device__ unsigned g_count;
__device__ volatile unsigned g_epoch;

// ---------------- shared memory (~217 KB) ----------------
struct __align__(16) Smem {
    ull   wt2[Hk / 2][HJ];          // W_rec slice, k-pair packed            128 KB
    float hbuf[BC][Hk];             // staged h (reused across phases)        16 KB
    float red[NW][BC][HJ];          // per-warp K partials (reused)           32 KB
    float hist[NGRP][BC][HJ][8];    // 8-step h history per group             32 KB
    float Win[HJ][INk];
    float bias[HJ];
    float Wk[OUTk][Hk];
    float bkey[OUTk];
    float x[NGRP][BC][INk];
    float key0[NGRP][BC];
    float kred[16][16];
};

union F2U { ull u; float2 f; };

__device__ __forceinline__ void fma2(ull& d, ull a, ull b) {
    asm("fma.rn.f32x2 %0, %1, %2, %0;" : "+l"(d) : "l"(a), "l"(b));
}
__device__ __forceinline__ int flag_acquire(const int* fp) {
    int v;
    asm volatile("ld.acquire.gpu.global.s32 %0, [%1];" : "=r"(v) : "l"(fp) : "memory");
    return v;
}
__device__ __forceinline__ void flag_release(int* fp, int v) {
    asm volatile("st.release.gpu.global.s32 [%0], %1;" :: "l"(fp), "r"(v) : "memory");
}
__device__ __forceinline__ void init_grid_barrier() {
    __syncthreads();
    if (threadIdx.x == 0) {
        __threadfence();
        unsigned e = g_epoch;
        if (atomicAdd(&g_count, 1u) == NCTA - 1u) {
            atomicExch(&g_count, 0u);
            __threadfence();
            g_epoch = e + 1u;
        } else {
            while (g_epoch == e) { }
            __threadfence();
        }
    }
    __syncthreads();
}

__global__ void __launch_bounds__(NTHR, 1)
rnn_dual_kernel(const float* __restrict__ inputs,   // [B][IN][T]
                const float* __restrict__ W_in,     // [H][IN]
                const float* __restrict__ b_in,
                const float* __restrict__ W_rec,    // [H][H]
                const float* __restrict__ b_rec,
                const float* __restrict__ W_key,    // [OUT][H]
                const float* __restrict__ b_key,
                float* __restrict__ out)
{
    extern __shared__ char smraw[];
    Smem& s = *reinterpret_cast<Smem*>(smraw);

    const int tid  = threadIdx.x;
    const int cta  = blockIdx.x;
    const int jb   = cta % JB;
    const int pair = cta / JB;
    const int jg0  = jb * HJ;
    const bool keyCTA = (jb == 0);

    float* keysOut = out;                                             // [B][2][T]
    float* prsOut  = out + (size_t)Bk * 2 * Tk;                       // [B][4][T]
    float* hsOut   = out + (size_t)Bk * 2 * Tk + (size_t)Bk * 4 * Tk; // [B][H][T]

    // ---------------- one-time init ----------------
    {
        const float2* wr2 = reinterpret_cast<const float2*>(W_rec);
        for (int idx = tid; idx < HJ * (Hk / 2); idx += NTHR) {
            int j  = idx >> 8;
            int k2 = idx & 255;
            F2U u; u.f = wr2[(size_t)(jg0 + j) * (Hk / 2) + k2];
            s.wt2[k2][j] = u.u;
        }
    }
    for (int idx = tid; idx < HJ * INk; idx += NTHR) {
        int j = idx / INk, i = idx % INk;
        s.Win[j][i] = W_in[(jg0 + j) * INk + i];
    }
    for (int j = tid; j < HJ; j += NTHR)
        s.bias[j] = b_in[jg0 + j] + b_rec[jg0 + j];
    if (keyCTA) {
        for (int idx = tid; idx < OUTk * Hk; idx += NTHR)
            s.Wk[idx / Hk][idx % Hk] = W_key[idx];
        if (tid < OUTk) s.bkey[tid] = b_key[tid];
        if (tid < NGRP * BC) s.key0[tid >> 3][tid & 7] = 1.0f;
        if (tid < NGRP * BC * 2) {   // keys column 0 = 0
            int g = tid >> 4, b = (tid >> 1) & 7, o = tid & 1;
            int bg = pair * 16 + g * 8 + b;
            keysOut[(size_t)bg * 2 * Tk + (size_t)o * Tk + 0] = 0.f;
        }
        if (tid < NGRP * BC * 4) {   // prs column 0 = 0
            int g = tid >> 5, b = (tid >> 2) & 7, c = tid & 3;
            int bg = pair * 16 + g * 8 + b;
            prsOut[(size_t)bg * 4 * Tk + (size_t)c * Tk + 0] = 0.f;
        }
    }
    // h[0] = 0, flags reset, hist slot 0 = 0 (both groups)
    for (int g = 0; g < NGRP; ++g)
        for (int o = tid; o < BC * HJ; o += NTHR)
            g_h[0][pair * 2 + g][jb][o] = 0.f;
    if (tid < NGRP) g_flag[pair * 2 + tid][jb][0] = 0;
    for (int o = tid; o < NGRP * BC * HJ; o += NTHR) {
        int g = o / (BC * HJ), r = o % (BC * HJ);
        s.hist[g][r >> 6][r & 63][0] = 0.f;
    }
    __syncthreads();
    init_grid_barrier();

    const int w    = tid >> 5;
    const int lane = tid & 31;
    const int jgrp = lane & 15;          // j0 = 4*jgrp
    const int b0   = (lane >> 4) * 4;    // 0 or 4
    const int srcSlice = w >> 1;         // producer slice this warp consumes
    const int jhalf = w & 1;

    const ulonglong2* w2row = reinterpret_cast<const ulonglong2*>(&s.wt2[0][0]); // [k2*32 + jpair]
    const ull*        hU    = reinterpret_cast<const ull*>(&s.hbuf[0][0]);       // [b*256 + k2]

    // ================ time loop: two interleaved groups ================
    for (int st = 0; st < STEPS; ++st) {
        const int par = st & 1;

        #pragma unroll
        for (int g = 0; g < NGRP; ++g) {
            const int bb  = pair * 2 + g;
            const int bg0 = pair * 16 + g * 8;

            // stage input column st+1 for this group
            if (tid < BC * INk) {
                int b = tid >> 3, i = tid & 7;
                s.x[g][b][i] =
                    inputs[(size_t)(bg0 + b) * INk * Tk + (size_t)i * Tk + (st + 1)];
            }

            // ---- per-warp: wait my k-slice's flag (usually already set), stage via L2 ----
            {
                const int* fp = (const int*)&g_flag[bb][srcSlice][0];
                while (flag_acquire(fp) < st) { }
                const float4* src = reinterpret_cast<const float4*>(&g_h[par][bb][srcSlice][0]);
                #pragma unroll
                for (int i = 0; i < 2; ++i) {
                    int e = lane + 32 * i;       // 0..63
                    int b = e >> 3, kq = e & 7;
                    float4 v = __ldcg(&src[b * 16 + jhalf * 8 + kq]);
                    *reinterpret_cast<float4*>(&s.hbuf[b][w * 32 + kq * 4]) = v;
                }
                __syncwarp();
            }

            // ---- matvec over this warp's 32-k slice (FFMA2) ----
            ull acc[4][4];
            #pragma unroll
            for (int i = 0; i < 4; ++i)
                #pragma unroll
                for (int jj = 0; jj < 4; ++jj) acc[i][jj] = 0ull;

            #pragma unroll
            for (int kk2 = 0; kk2 < 16; ++kk2) {
                const int k2 = w * 16 + kk2;
                ulonglong2 wA = w2row[k2 * 32 + jgrp * 2];
                ulonglong2 wB = w2row[k2 * 32 + jgrp * 2 + 1];
                #pragma unroll
                for (int i = 0; i < 4; ++i) {
                    ull hh = hU[(b0 + i) * 256 + k2];
                    fma2(acc[i][0], wA.x, hh);
                    fma2(acc[i][1], wA.y, hh);
                    fma2(acc[i][2], wB.x, hh);
                    fma2(acc[i][3], wB.y, hh);
                }
            }
            #pragma unroll
            for (int i = 0; i < 4; ++i) {
                float r[4];
                #pragma unroll
                for (int jj = 0; jj < 4; ++jj) {
                    F2U u; u.u = acc[i][jj];
                    r[jj] = u.f.x + u.f.y;
                }
                *reinterpret_cast<float4*>(&s.red[w][b0 + i][jgrp * 4]) =
                    make_float4(r[0], r[1], r[2], r[3]);
            }
            __syncthreads();   // bar1: red + hbuf + x staged

            // ---- finalize h[st+1]; keyCTA computes key partials from hbuf = h[st] ----
            {
                int b = tid >> 6, j = tid & 63;
                float v = s.bias[j];
                #pragma unroll
                for (int ww = 0; ww < NW; ++ww) v += s.red[ww][b][j];
                #pragma unroll
                for (int i = 0; i < INk; ++i) v = fmaf(s.x[g][b][i], s.Win[j][i], v);
                float h = tanhf(v);
                g_h[par ^ 1][bb][jb][tid] = h;
                s.hist[g][b][j][(st + 1) & 7] = h;
            }
            if (keyCTA && st >= 1 && tid < 256) {
                int p = tid >> 4, kg = tid & 15;     // p = b*2+o
                int b = p >> 1, o = p & 1;
                float acck = 0.f;
                #pragma unroll
                for (int kk = 0; kk < 32; ++kk) {
                    int k = kg * 32 + kk;
                    acck = fmaf(s.hbuf[b][k], s.Wk[o][k], acck);
                }
                s.kred[p][kg] = acck;
            }
            __syncthreads();   // bar2: h STGs + kred done

            // publish this group's slice
            if (tid == 0) flag_release(&g_flag[bb][jb][0], st + 1);

            // ---- keys + prs (keyCTA, warp0) ----
            if (keyCTA) {
                if (st >= 1 && tid < 16) {
                    int b2 = tid >> 1, o2 = tid & 1;
                    float z = s.bkey[o2];
                    #pragma unroll
                    for (int gg = 0; gg < 16; ++gg) z += s.kred[tid][gg];
                    float kv = 1.f / (1.f + expf(-z));
                    keysOut[(size_t)(bg0 + b2) * 2 * Tk + (size_t)o2 * Tk + st] = kv;
                    if (o2 == 0) s.key0[g][b2] = kv;
                }
                if (tid < 32) {
                    __syncwarp();
                    int b = tid >> 2, c = tid & 3;
                    float kp = s.key0[g][b];         // 1.0 at st=0, else key[st-1]
                    float tm, arm;
                    if (c < 2) { tm = s.x[g][b][6]; arm = s.x[g][b][c]; }
                    else       { tm = s.x[g][b][7];
                                 arm = s.x[g][b][c] * kp + s.x[g][b][c + 2] * (1.f - kp); }
                    float d = (tm - arm) / (0.15f * arm);
                    float v = (tm == 0.f) ? 0.f : d * d;
                    prsOut[(size_t)(bg0 + b) * 4 * Tk + (size_t)c * Tk + (st + 1)] = v;
                }
            }

            // ---- flush 8-step history (same-thread slots; after bar2) ----
            if (((st + 1) & 7) == 7) {
                const int base = st - 6;
                int b = tid >> 6, j = tid & 63;
                float4 lo = *reinterpret_cast<float4*>(&s.hist[g][b][j][0]);
                float4 hi = *reinterpret_cast<float4*>(&s.hist[g][b][j][4]);
                float* dst = &hsOut[(size_t)(bg0 + b) * Hk * Tk +
                                    (size_t)(jg0 + j) * Tk + base];
                *reinterpret_cast<float4*>(dst)     = lo;
                *reinterpret_cast<float4*>(dst + 4) = hi;
            }
        }
    }

    // ================ epilogue: keys[:,:,1023] = sigmoid(Wk h[1023]) ================
    if (keyCTA) {
        for (int g = 0; g < NGRP; ++g) {
            const int bb  = pair * 2 + g;
            const int bg0 = pair * 16 + g * 8;
            {
                const int* fp = (const int*)&g_flag[bb][srcSlice][0];
                while (flag_acquire(fp) < STEPS) { }
                const float4* src =
                    reinterpret_cast<const float4*>(&g_h[STEPS & 1][bb][srcSlice][0]);
                #pragma unroll
                for (int i = 0; i < 2; ++i) {
                    int e = lane + 32 * i;
                    int b = e >> 3, kq = e & 7;
                    float4 v = __ldcg(&src[b * 16 + jhalf * 8 + kq]);
                    *reinterpret_cast<float4*>(&s.hbuf[b][w * 32 + kq * 4]) = v;
                }
            }
            __syncthreads();
            if (tid < 256) {
                int p = tid >> 4, kg = tid & 15;
                int b = p >> 1, o = p & 1;
                float acck = 0.f;
                #pragma unroll
                for (int kk = 0; kk < 32; ++kk) {
                    int k = kg * 32 + kk;
                    acck = fmaf(s.hbuf[b][k], s.Wk[o][k], acck);
                }
                s.kred[p][kg] = acck;
            }
            __syncthreads();
            if (tid < 16) {
                int b2 = tid >> 1, o2 = tid & 1;
                float z = s.bkey[o2];
                #pragma unroll
                for (int gg = 0; gg < 16; ++gg) z += s.kred[tid][gg];
                float kv = 1.f / (1.f + expf(-z));
                keysOut[(size_t)(bg0 + b2) * 2 * Tk + (size_t)o2 * Tk + (Tk - 1)] = kv;
            }
            __syncthreads();
        }
    }
}

extern "C" void kernel_launch(void* const* d_in, const int* in_sizes, int n_in,
                              void* d_out, int out_size) {
    const float* inputs = (const float*)d_in[0];
    const float* W_in   = (const float*)d_in[1];
    const float* b_in   = (const float*)d_in[2];
    const float* W_rec  = (const float*)d_in[3];
    const float* b_rec  = (const float*)d_in[4];
    const float* W_key  = (const float*)d_in[5];
    const float* b_key  = (const float*)d_in[6];
    float* out = (float*)d_out;

    static bool attr_set = false;
    if (!attr_set) {
        cudaFuncSetAttribute(rnn_dual_kernel,
                             cudaFuncAttributeMaxDynamicSharedMemorySize,
                             (int)sizeof(Smem));
        attr_set = true;
    }
    rnn_dual_kernel<<<NCTA, NTHR, sizeof(Smem)>>>(
        inputs, W_in, b_in, W_rec, b_rec, W_key, b_key, out);
}

// round 8
// speedup vs baseline: 1.3863x; 1.3863x over previous
#include <cuda_runtime.h>
#include <math.h>
#include <stdint.h>

#define Bk   128
#define Hk   512
#define Tk   1024
#define INk  8
#define OUTk 2

#define JB   8          // j-slice CTAs per batch-group (producer slices, 64 j each)
#define BBL  16         // batch-groups
#define HJ   64         // H / JB
#define BC   8          // batches per CTA
#define NCTA 128
#define NTHR 1024       // 32 warps
#define NKG  16         // k-groups (32 k each)
#define STEPS (Tk - 1)

typedef unsigned long long ull;

// ---------------- device globals ----------------
__device__ float g_h[2][BBL][JB][BC * HJ];     // h ping-pong, sliced by producer jb
__device__ int   g_flag[BBL][JB][8];           // latest published step per (bb, jb)
__device__ unsigned g_count;
__device__ volatile unsigned g_epoch;

// ---------------- shared memory (~182 KB) ----------------
struct __align__(16) Smem {
    ull   wt2[Hk / 2][HJ];        // W_rec slice, k-pair packed            128 KB
    float hbuf[BC][Hk];           // staged h_pre                           16 KB
    float red[NKG][BC][HJ];       // per-kgroup K partials                  16 KB
    float hist[BC][HJ][8];        // 8-step h history                       16 KB
    float Win[HJ][INk];
    float bias[HJ];
    float Wk[OUTk][Hk];
    float bkey[OUTk];
    float x[2][BC][INk];
    float key0[BC];
    float kred[16][16];
};

union F2U { ull u; float2 f; };

__device__ __forceinline__ void fma2(ull& d, ull a, ull b) {
    asm("fma.rn.f32x2 %0, %1, %2, %0;" : "+l"(d) : "l"(a), "l"(b));
}
__device__ __forceinline__ int flag_acquire(const int* fp) {
    int v;
    asm volatile("ld.acquire.gpu.global.s32 %0, [%1];" : "=r"(v) : "l"(fp) : "memory");
    return v;
}
__device__ __forceinline__ void flag_release(int* fp, int v) {
    asm volatile("st.release.gpu.global.s32 [%0], %1;" :: "l"(fp), "r"(v) : "memory");
}
__device__ __forceinline__ void init_grid_barrier() {
    __syncthreads();
    if (threadIdx.x == 0) {
        __threadfence();
        unsigned e = g_epoch;
        if (atomicAdd(&g_count, 1u) == NCTA - 1u) {
            atomicExch(&g_count, 0u);
            __threadfence();
            g_epoch = e + 1u;
        } else {
            while (g_epoch == e) { }
            __threadfence();
        }
    }
    __syncthreads();
}

__global__ void __launch_bounds__(NTHR, 1)
rnn_wide_kernel(const float* __restrict__ inputs,   // [B][IN][T]
                const float* __restrict__ W_in,     // [H][IN]
                const float* __restrict__ b_in,
                const float* __restrict__ W_rec,    // [H][H]
                const float* __restrict__ b_rec,
                const float* __restrict__ W_key,    // [OUT][H]
                const float* __restrict__ b_key,
                float* __restrict__ out)
{
    extern __shared__ char smraw[];
    Smem& s = *reinterpret_cast<Smem*>(smraw);

    const int tid = threadIdx.x;
    const int cta = blockIdx.x;
    const int jb  = cta % JB;
    const int bb  = cta / JB;
    const int jg0 = jb * HJ;
    const int bg0 = bb * BC;
    const bool keyCTA = (jb == 0);

    float* keysOut = out;                                             // [B][2][T]
    float* prsOut  = out + (size_t)Bk * 2 * Tk;                       // [B][4][T]
    float* hsOut   = out + (size_t)Bk * 2 * Tk + (size_t)Bk * 4 * Tk; // [B][H][T]

    // ---------------- one-time init ----------------
    {
        const float2* wr2 = reinterpret_cast<const float2*>(W_rec);
        for (int idx = tid; idx < HJ * (Hk / 2); idx += NTHR) {
            int j  = idx >> 8;
            int k2 = idx & 255;
            F2U u; u.f = wr2[(size_t)(jg0 + j) * (Hk / 2) + k2];
            s.wt2[k2][j] = u.u;
        }
    }
    for (int idx = tid; idx < HJ * INk; idx += NTHR) {
        int j = idx / INk, i = idx % INk;
        s.Win[j][i] = W_in[(jg0 + j) * INk + i];
    }
    for (int j = tid; j < HJ; j += NTHR)
        s.bias[j] = b_in[jg0 + j] + b_rec[jg0 + j];
    if (keyCTA) {
        for (int idx = tid; idx < OUTk * Hk; idx += NTHR)
            s.Wk[idx / Hk][idx % Hk] = W_key[idx];
        if (tid < OUTk) s.bkey[tid] = b_key[tid];
        if (tid < BC) s.key0[tid] = 1.0f;
        if (tid < BC * 2) {
            int b = tid >> 1, o = tid & 1;
            keysOut[(size_t)(bg0 + b) * 2 * Tk + (size_t)o * Tk + 0] = 0.f;
        }
        if (tid < BC * 4) {
            int b = tid >> 2, c = tid & 3;
            prsOut[(size_t)(bg0 + b) * 4 * Tk + (size_t)c * Tk + 0] = 0.f;
        }
    }
    if (tid < BC * HJ)
        g_h[0][bb][jb][tid] = 0.f;
    if (tid == 0) g_flag[bb][jb][0] = 0;
    if (tid < BC * HJ) {
        int b = tid >> 6, j = tid & 63;
        s.hist[b][j][0] = 0.f;
    }
    __syncthreads();
    init_grid_barrier();

    // ---------------- warp decomposition: 32 warps = 16 kgrp x 2 jhalf ----------------
    const int w    = tid >> 5;
    const int kgrp = w >> 1;             // k in [kgrp*32, +32)
    const int jh   = w & 1;              // j in [jh*32, +32)
    const int lane = tid & 31;
    const int jq   = lane & 7;           // 4 j's: j0 = jh*32 + jq*4
    const int bq   = lane >> 3;          // batches bq*2, bq*2+1
    const int srcSlice = kgrp >> 1;      // producer slice (64 j wide)
    const int khalf    = kgrp & 1;       // which 32-k half of that slice

    const int* srcFlag = &g_flag[bb][srcSlice][0];
    const ulonglong2* w2row = reinterpret_cast<const ulonglong2*>(&s.wt2[0][0]); // [k2*32 + jpair]
    const ull*        hU    = reinterpret_cast<const ull*>(&s.hbuf[0][0]);       // [b*256 + k2]

    // ================ time loop ================
    for (int st = 0; st < STEPS; ++st) {
        const int par = st & 1;
        const int xp  = st & 1;

        // stage input column st+1
        if (tid < BC * INk) {
            int b = tid >> 3, i = tid & 7;
            s.x[xp][b][i] = inputs[(size_t)(bg0 + b) * INk * Tk + (size_t)i * Tk + (st + 1)];
        }

        // ---- per-warp: wait producer flag, stage this warp's 32-k slab (1 KB) ----
        {
            while (flag_acquire(srcFlag) < st) { }
            const float4* src = reinterpret_cast<const float4*>(&g_h[par][bb][srcSlice][0]);
            #pragma unroll
            for (int i = 0; i < 2; ++i) {
                int e = lane + 32 * i;       // 0..63 = (b, q)
                int b = e >> 3, q = e & 7;
                float4 v = __ldcg(&src[b * 16 + khalf * 8 + q]);
                *reinterpret_cast<float4*>(&s.hbuf[b][kgrp * 32 + q * 4]) = v;
            }
            __syncwarp();
        }

        // ---- matvec: 32-k x 32-j x (2 batches/lane), FFMA2 ----
        ull acc[2][4];
        #pragma unroll
        for (int i = 0; i < 2; ++i)
            #pragma unroll
            for (int jj = 0; jj < 4; ++jj) acc[i][jj] = 0ull;

        #pragma unroll
        for (int kk2 = 0; kk2 < 16; ++kk2) {
            const int k2 = kgrp * 16 + kk2;
            ulonglong2 wA = w2row[k2 * 32 + jh * 16 + jq * 2];
            ulonglong2 wB = w2row[k2 * 32 + jh * 16 + jq * 2 + 1];
            ull h0 = hU[(bq * 2 + 0) * 256 + k2];
            ull h1 = hU[(bq * 2 + 1) * 256 + k2];
            fma2(acc[0][0], wA.x, h0); fma2(acc[0][1], wA.y, h0);
            fma2(acc[0][2], wB.x, h0); fma2(acc[0][3], wB.y, h0);
            fma2(acc[1][0], wA.x, h1); fma2(acc[1][1], wA.y, h1);
            fma2(acc[1][2], wB.x, h1); fma2(acc[1][3], wB.y, h1);
        }
        #pragma unroll
        for (int i = 0; i < 2; ++i) {
            float r[4];
            #pragma unroll
            for (int jj = 0; jj < 4; ++jj) {
                F2U u; u.u = acc[i][jj];
                r[jj] = u.f.x + u.f.y;
            }
            *reinterpret_cast<float4*>(&s.red[kgrp][bq * 2 + i][jh * 32 + jq * 4]) =
                make_float4(r[0], r[1], r[2], r[3]);
        }
        __syncthreads();   // bar1: red + hbuf + x staged

        // ---- finalize h[st+1] (512 outputs); keyCTA key partials from hbuf ----
        if (tid < BC * HJ) {
            int b = tid >> 6, j = tid & 63;
            float v = s.bias[j];
            #pragma unroll
            for (int kk = 0; kk < NKG; ++kk) v += s.red[kk][b][j];
            #pragma unroll
            for (int i = 0; i < INk; ++i) v = fmaf(s.x[xp][b][i], s.Win[j][i], v);
            float h = tanhf(v);
            g_h[par ^ 1][bb][jb][tid] = h;
            s.hist[b][j][(st + 1) & 7] = h;
        } else if (keyCTA && st >= 1 && tid < 768) {
            int p = (tid - 512) >> 4, kg = tid & 15;    // p = b*2+o
            int b = p >> 1, o = p & 1;
            float acck = 0.f;
            #pragma unroll
            for (int kk = 0; kk < 32; ++kk) {
                int k = kg * 32 + kk;
                acck = fmaf(s.hbuf[b][k], s.Wk[o][k], acck);
            }
            s.kred[p][kg] = acck;
        }
        __syncthreads();   // bar2: h STGs + kred done

        // publish
        if (tid == 0) flag_release(&g_flag[bb][jb][0], st + 1);

        // ---- keys + prs (keyCTA, warp0) ----
        if (keyCTA) {
            if (st >= 1 && tid < 16) {
                int b2 = tid >> 1, o2 = tid & 1;
                float z = s.bkey[o2];
                #pragma unroll
                for (int g = 0; g < 16; ++g) z += s.kred[tid][g];
                float kv = 1.f / (1.f + expf(-z));
                keysOut[(size_t)(bg0 + b2) * 2 * Tk + (size_t)o2 * Tk + st] = kv;
                if (o2 == 0) s.key0[b2] = kv;
            }
            if (tid < 32) {
                __syncwarp();
                int b = tid >> 2, c = tid & 3;
                float kp = s.key0[b];               // 1.0 at st=0, else key[st-1]
                float tm, arm;
                if (c < 2) { tm = s.x[xp][b][6]; arm = s.x[xp][b][c]; }
                else       { tm = s.x[xp][b][7];
                             arm = s.x[xp][b][c] * kp + s.x[xp][b][c + 2] * (1.f - kp); }
                float d = (tm - arm) / (0.15f * arm);
                float v = (tm == 0.f) ? 0.f : d * d;
                prsOut[(size_t)(bg0 + b) * 4 * Tk + (size_t)c * Tk + (st + 1)] = v;
            }
        }

        // ---- flush 8-step history (same-thread slots; after bar2) ----
        if (((st + 1) & 7) == 7 && tid < BC * HJ) {
            const int base = st - 6;
            int b = tid >> 6, j = tid & 63;
            float4 lo = *reinterpret_cast<float4*>(&s.hist[b][j][0]);
            float4 hi = *reinterpret_cast<float4*>(&s.hist[b][j][4]);
            float* dst = &hsOut[(size_t)(bg0 + b) * Hk * Tk + (size_t)(jg0 + j) * Tk + base];
            *reinterpret_cast<float4*>(dst)     = lo;
            *reinterpret_cast<float4*>(dst + 4) = hi;
        }
    }

    // ================ epilogue: keys[:,:,1023] = sigmoid(Wk h[1023]) ================
    if (keyCTA) {
        {
            while (flag_acquire(srcFlag) < STEPS) { }
            const float4* src = reinterpret_cast<const float4*>(&g_h[STEPS & 1][bb][srcSlice][0]);
            #pragma unroll
            for (int i = 0; i < 2; ++i) {
                int e = lane + 32 * i;
                int b = e >> 3, q = e & 7;
                float4 v = __ldcg(&src[b * 16 + khalf * 8 + q]);
                *reinterpret_cast<float4*>(&s.hbuf[b][kgrp * 32 + q * 4]) = v;
            }
        }
        __syncthreads();
        if (tid < 256) {
            int p = tid >> 4, kg = tid & 15;
            int b = p >> 1, o = p & 1;
            float acck = 0.f;
            #pragma unroll
            for (int kk = 0; kk < 32; ++kk) {
                int k = kg * 32 + kk;
                acck = fmaf(s.hbuf[b][k], s.Wk[o][k], acck);
            }
            s.kred[p][kg] = acck;
        }
        __syncthreads();
        if (tid < 16) {
            int b2 = tid >> 1, o2 = tid & 1;
            float z = s.bkey[o2];
            #pragma unroll
            for (int g = 0; g < 16; ++g) z += s.kred[tid][g];
            float kv = 1.f / (1.f + expf(-z));
            keysOut[(size_t)(bg0 + b2) * 2 * Tk + (size_t)o2 * Tk + (Tk - 1)] = kv;
        }
    }
}

extern "C" void kernel_launch(void* const* d_in, const int* in_sizes, int n_in,
                              void* d_out, int out_size) {
    const float* inputs = (const float*)d_in[0];
    const float* W_in   = (const float*)d_in[1];
    const float* b_in   = (const float*)d_in[2];
    const float* W_rec  = (const float*)d_in[3];
    const float* b_rec  = (const float*)d_in[4];
    const float* W_key  = (const float*)d_in[5];
    const float* b_key  = (const float*)d_in[6];
    float* out = (float*)d_out;

    static bool attr_set = false;
    if (!attr_set) {
        cudaFuncSetAttribute(rnn_wide_kernel,
                             cudaFuncAttributeMaxDynamicSharedMemorySize,
                             (int)sizeof(Smem));
        attr_set = true;
    }
    rnn_wide_kernel<<<NCTA, NTHR, sizeof(Smem)>>>(
        inputs, W_in, b_in, W_rec, b_rec, W_key, b_key, out);
}

// round 9
// speedup vs baseline: 2.3743x; 1.7126x over previous
#include <cuda_runtime.h>
#include <math.h>
#include <stdint.h>

#define Bk   128
#define Hk   512
#define Tk   1024
#define INk  8
#define OUTk 2

#define JB   8          // j-slice CTAs per batch-group
#define BBL  16         // batch-groups
#define HJ   64         // H / JB
#define BC   8          // batches per CTA
#define NCTA 128
#define NTHR 512        // 16 warps
#define NW   16
#define RPAD 17         // red row stride (floats), odd -> conflict-free columns
#define STEPS (Tk - 1)

typedef unsigned long long ull;

// ---------------- device globals ----------------
__device__ float g_h[2][BBL][JB][BC * HJ];     // h ping-pong, sliced by producer jb
__device__ int   g_flag[BBL][JB][8];           // latest published step per (bb, jb)
__device__ unsigned g_count;
__device__ volatile unsigned g_epoch;

// ---------------- shared memory (~75 KB; weights now in registers) ----------------
struct __align__(16) Smem {
    float hbuf[BC][Hk];             // staged h_pre                         16 KB
    float red[BC * HJ][RPAD];       // 16 k-partials per output, padded     ~34 KB
    float hist[BC][HJ][8];          // 8-step h history                      16 KB
    float Win[HJ][INk];
    float bias[HJ];
    float Wk[OUTk][Hk];
    float bkey[OUTk];
    float x[2][BC][INk];
    float key0[BC];
    float kred[16][16];
};

union F2U { ull u; float2 f; };

__device__ __forceinline__ void fma2(ull& d, ull a, ull b) {
    asm("fma.rn.f32x2 %0, %1, %2, %0;" : "+l"(d) : "l"(a), "l"(b));
}
__device__ __forceinline__ int flag_acquire(const int* fp) {
    int v;
    asm volatile("ld.acquire.gpu.global.s32 %0, [%1];" : "=r"(v) : "l"(fp) : "memory");
    return v;
}
__device__ __forceinline__ void flag_release(int* fp, int v) {
    asm volatile("st.release.gpu.global.s32 [%0], %1;" :: "l"(fp), "r"(v) : "memory");
}
__device__ __forceinline__ void init_grid_barrier() {
    __syncthreads();
    if (threadIdx.x == 0) {
        __threadfence();
        unsigned e = g_epoch;
        if (atomicAdd(&g_count, 1u) == NCTA - 1u) {
            atomicExch(&g_count, 0u);
            __threadfence();
            g_epoch = e + 1u;
        } else {
            while (g_epoch == e) { }
            __threadfence();
        }
    }
    __syncthreads();
}

__global__ void __launch_bounds__(NTHR, 1)
rnn_regw_kernel(const float* __restrict__ inputs,   // [B][IN][T]
                const float* __restrict__ W_in,     // [H][IN]
                const float* __restrict__ b_in,
                const float* __restrict__ W_rec,    // [H][H]
                const float* __restrict__ b_rec,
                const float* __restrict__ W_key,    // [OUT][H]
                const float* __restrict__ b_key,
                float* __restrict__ out)
{
    extern __shared__ char smraw[];
    Smem& s = *reinterpret_cast<Smem*>(smraw);

    const int tid = threadIdx.x;
    const int cta = blockIdx.x;
    const int jb  = cta % JB;
    const int bb  = cta / JB;
    const int jg0 = jb * HJ;
    const int bg0 = bb * BC;
    const bool keyCTA = (jb == 0);

    float* keysOut = out;                                             // [B][2][T]
    float* prsOut  = out + (size_t)Bk * 2 * Tk;                       // [B][4][T]
    float* hsOut   = out + (size_t)Bk * 2 * Tk + (size_t)Bk * 4 * Tk; // [B][H][T]

    // ---------------- thread mapping ----------------
    const int w    = tid >> 5;           // warp 0..15; k2 range [16w, 16w+16)
    const int lane = tid & 31;
    const int jq   = lane & 15;          // j-quad: j = jq*4 + jj
    const int ksl  = lane >> 4;          // ks_lsb
    const int ks   = 2 * w + ksl;        // 0..31; thread k2 = ks*8 + i (i<8)
    const int srcSlice = w >> 1;         // producer slice for this warp's k-range
    const int jhalf    = w & 1;

    // ---------------- register-resident weights: w2r[i][jj] = (W[j][2k2], W[j][2k2+1]) ----
    ull w2r[8][4];
    {
        #pragma unroll
        for (int jj = 0; jj < 4; ++jj) {
            const float2* row = reinterpret_cast<const float2*>(
                W_rec + (size_t)(jg0 + jq * 4 + jj) * Hk);
            #pragma unroll
            for (int i = 0; i < 8; ++i) {
                F2U u; u.f = row[ks * 8 + i];
                w2r[i][jj] = u.u;
            }
        }
    }

    // ---------------- one-time init ----------------
    for (int idx = tid; idx < HJ * INk; idx += NTHR) {
        int j = idx / INk, i = idx % INk;
        s.Win[j][i] = W_in[(jg0 + j) * INk + i];
    }
    for (int j = tid; j < HJ; j += NTHR)
        s.bias[j] = b_in[jg0 + j] + b_rec[jg0 + j];
    if (keyCTA) {
        for (int idx = tid; idx < OUTk * Hk; idx += NTHR)
            s.Wk[idx / Hk][idx % Hk] = W_key[idx];
        if (tid < OUTk) s.bkey[tid] = b_key[tid];
        if (tid < BC) s.key0[tid] = 1.0f;
        if (tid < BC * 2) {
            int b = tid >> 1, o = tid & 1;
            keysOut[(size_t)(bg0 + b) * 2 * Tk + (size_t)o * Tk + 0] = 0.f;
        }
        if (tid < BC * 4) {
            int b = tid >> 2, c = tid & 3;
            prsOut[(size_t)(bg0 + b) * 4 * Tk + (size_t)c * Tk + 0] = 0.f;
        }
    }
    if (tid < BC * HJ) {
        g_h[0][bb][jb][tid] = 0.f;
        int b = tid >> 6, j = tid & 63;
        s.hist[b][j][0] = 0.f;
    }
    if (tid == 0) g_flag[bb][jb][0] = 0;
    __syncthreads();
    init_grid_barrier();

    const int* srcFlag = &g_flag[bb][srcSlice][0];
    const ull* hU = reinterpret_cast<const ull*>(&s.hbuf[0][0]);   // [b*256 + k2]

    // ================ time loop ================
    for (int st = 0; st < STEPS; ++st) {
        const int par = st & 1;
        const int xp  = st & 1;

        // stage input column st+1
        if (tid < BC * INk) {
            int b = tid >> 3, i = tid & 7;
            s.x[xp][b][i] = inputs[(size_t)(bg0 + b) * INk * Tk + (size_t)i * Tk + (st + 1)];
        }

        // ---- per-warp: wait producer flag, stage this warp's 32-k slab ----
        {
            while (flag_acquire(srcFlag) < st) { }
            const float4* src = reinterpret_cast<const float4*>(&g_h[par][bb][srcSlice][0]);
            #pragma unroll
            for (int i = 0; i < 2; ++i) {
                int e = lane + 32 * i;       // 0..63 = (b, q)
                int b = e >> 3, q = e & 7;
                float4 v = __ldcg(&src[b * 16 + jhalf * 8 + q]);
                *reinterpret_cast<float4*>(&s.hbuf[b][w * 32 + q * 4]) = v;
            }
            __syncwarp();
        }

        // ---- matvec: register weights x broadcast-LDS h; 2 passes of 4 batches ----
        #pragma unroll
        for (int p = 0; p < 2; ++p) {
            ull acc[4][4];
            #pragma unroll
            for (int bi = 0; bi < 4; ++bi)
                #pragma unroll
                for (int jj = 0; jj < 4; ++jj) acc[bi][jj] = 0ull;

            #pragma unroll
            for (int bi = 0; bi < 4; ++bi) {
                const ull* hb = &hU[(p * 4 + bi) * 256 + ks * 8];
                #pragma unroll
                for (int i = 0; i < 8; ++i) {
                    ull h2 = hb[i];
                    fma2(acc[bi][0], w2r[i][0], h2);
                    fma2(acc[bi][1], w2r[i][1], h2);
                    fma2(acc[bi][2], w2r[i][2], h2);
                    fma2(acc[bi][3], w2r[i][3], h2);
                }
            }
            // pair + k-reduce across ks_lsb (xor 16), then write 16th partial
            #pragma unroll
            for (int bi = 0; bi < 4; ++bi) {
                #pragma unroll
                for (int jj = 0; jj < 4; ++jj) {
                    F2U u; u.u = acc[bi][jj];
                    float f = u.f.x + u.f.y;
                    f += __shfl_xor_sync(0xffffffffu, f, 16);
                    // lanes with ksl==0 write bi 0,1; ksl==1 write bi 2,3
                    if ((bi >> 1) == ksl) {
                        int b = p * 4 + bi;
                        s.red[b * HJ + jq * 4 + jj][w] = f;
                    }
                }
            }
        }
        __syncthreads();   // bar1: red + hbuf + x staged

        // ---- finalize h[st+1] (one output per thread); keyCTA key partials ----
        {
            int b = tid >> 6, j = tid & 63;
            float v = s.bias[j];
            #pragma unroll
            for (int kw = 0; kw < NW; ++kw) v += s.red[tid][kw];
            #pragma unroll
            for (int i = 0; i < INk; ++i) v = fmaf(s.x[xp][b][i], s.Win[j][i], v);
            float h = tanhf(v);
            g_h[par ^ 1][bb][jb][tid] = h;
            s.hist[b][j][(st + 1) & 7] = h;
        }
        if (keyCTA && st >= 1 && tid < 256) {
            int p = tid >> 4, kg = tid & 15;     // p = b*2+o
            int b = p >> 1, o = p & 1;
            float acck = 0.f;
            #pragma unroll
            for (int kk = 0; kk < 32; ++kk) {
                int k = kg * 32 + kk;
                acck = fmaf(s.hbuf[b][k], s.Wk[o][k], acck);
            }
            s.kred[p][kg] = acck;
        }
        __syncthreads();   // bar2: h STGs + kred done

        // publish
        if (tid == 0) flag_release(&g_flag[bb][jb][0], st + 1);

        // ---- keys + prs (keyCTA, warp0) ----
        if (keyCTA) {
            if (st >= 1 && tid < 16) {
                int b2 = tid >> 1, o2 = tid & 1;
                float z = s.bkey[o2];
                #pragma unroll
                for (int g = 0; g < 16; ++g) z += s.kred[tid][g];
                float kv = 1.f / (1.f + expf(-z));
                keysOut[(size_t)(bg0 + b2) * 2 * Tk + (size_t)o2 * Tk + st] = kv;
                if (o2 == 0) s.key0[b2] = kv;
            }
            if (tid < 32) {
                __syncwarp();
                int b = tid >> 2, c = tid & 3;
                float kp = s.key0[b];               // 1.0 at st=0, else key[st-1]
                float tm, arm;
                if (c < 2) { tm = s.x[xp][b][6]; arm = s.x[xp][b][c]; }
                else       { tm = s.x[xp][b][7];
                             arm = s.x[xp][b][c] * kp + s.x[xp][b][c + 2] * (1.f - kp); }
                float d = (tm - arm) / (0.15f * arm);
                float v = (tm == 0.f) ? 0.f : d * d;
                prsOut[(size_t)(bg0 + b) * 4 * Tk + (size_t)c * Tk + (st + 1)] = v;
            }
        }

        // ---- flush 8-step history (same-thread slots; after bar2) ----
        if (((st + 1) & 7) == 7) {
            const int base = st - 6;
            int b = tid >> 6, j = tid & 63;
            float4 lo = *reinterpret_cast<float4*>(&s.hist[b][j][0]);
            float4 hi = *reinterpret_cast<float4*>(&s.hist[b][j][4]);
            float* dst = &hsOut[(size_t)(bg0 + b) * Hk * Tk + (size_t)(jg0 + j) * Tk + base];
            *reinterpret_cast<float4*>(dst)     = lo;
            *reinterpret_cast<float4*>(dst + 4) = hi;
        }
    }

    // ================ epilogue: keys[:,:,1023] = sigmoid(Wk h[1023]) ================
    if (keyCTA) {
        {
            while (flag_acquire(srcFlag) < STEPS) { }
            const float4* src = reinterpret_cast<const float4*>(&g_h[STEPS & 1][bb][srcSlice][0]);
            #pragma unroll
            for (int i = 0; i < 2; ++i) {
                int e = lane + 32 * i;
                int b = e >> 3, q = e & 7;
                float4 v = __ldcg(&src[b * 16 + jhalf * 8 + q]);
                *reinterpret_cast<float4*>(&s.hbuf[b][w * 32 + q * 4]) = v;
            }
        }
        __syncthreads();
        if (tid < 256) {
            int p = tid >> 4, kg = tid & 15;
            int b = p >> 1, o = p & 1;
            float acck = 0.f;
            #pragma unroll
            for (int kk = 0; kk < 32; ++kk) {
                int k = kg * 32 + kk;
                acck = fmaf(s.hbuf[b][k], s.Wk[o][k], acck);
            }
            s.kred[p][kg] = acck;
        }
        __syncthreads();
        if (tid < 16) {
            int b2 = tid >> 1, o2 = tid & 1;
            float z = s.bkey[o2];
            #pragma unroll
            for (int g = 0; g < 16; ++g) z += s.kred[tid][g];
            float kv = 1.f / (1.f + expf(-z));
            keysOut[(size_t)(bg0 + b2) * 2 * Tk + (size_t)o2 * Tk + (Tk - 1)] = kv;
        }
    }
}

extern "C" void kernel_launch(void* const* d_in, const int* in_sizes, int n_in,
                              void* d_out, int out_size) {
    const float* inputs = (const float*)d_in[0];
    const float* W_in   = (const float*)d_in[1];
    const float* b_in   = (const float*)d_in[2];
    const float* W_rec  = (const float*)d_in[3];
    const float* b_rec  = (const float*)d_in[4];
    const float* W_key  = (const float*)d_in[5];
    const float* b_key  = (const float*)d_in[6];
    float* out = (float*)d_out;

    static bool attr_set = false;
    if (!attr_set) {
        cudaFuncSetAttribute(rnn_regw_kernel,
                             cudaFuncAttributeMaxDynamicSharedMemorySize,
                             (int)sizeof(Smem));
        attr_set = true;
    }
    rnn_regw_kernel<<<NCTA, NTHR, sizeof(Smem)>>>(
        inputs, W_in, b_in, W_rec, b_rec, W_key, b_key, out);
}